// round 6
// baseline (speedup 1.0000x reference)
#include <cuda_runtime.h>

#define NN  192
#define NN2 (NN*NN)
#define NN3 (NN*NN*NN)

#define INV2DX     96.0f          // 1/(2*dx), dx = 1/N
#define MU_REF_F   1.8e-5f
#define CP_OVER_PR 1395.833333f   // 1005 / 0.72

#define TX 32
#define TY 8
#define CHUNK 48
#define PX  (TX + 2)              // 34  flux plane (halo 1)
#define PY  (TY + 2)              // 10
#define PX2 (TX + 4)              // 36  u/T plane (halo 2)
#define PY2 (TY + 4)              // 12
#define NPTS   (PX * PY)          // 340 flux points
#define NHALO  (NPTS - TX * TY)   // 84  halo-ring flux points
#define NSTG   (PX2 * PX2 > 0 ? PX2 * PY2 : 0)   // 432 staging points
#define NTHREADS (TX * TY)        // 256

#define SU_PLANE  (4 * PY2 * PX2) // 1728 floats per u/T plane slot
#define SFH_PLANE (7 * PY * PX)   // 2380 floats: t01,t02,t11,t12,t22,E1,E2
#define SMEM_FLOATS (4 * SU_PLANE + 3 * SFH_PLANE)   // 6912 + 7140 = 14052
#define SMEM_BYTES  (SMEM_FLOATS * 4)                // 56208

__device__ __forceinline__ int wrapg(int i) { return (i < 0) ? i + NN : ((i >= NN) ? i - NN : i); }
// p >= -2 always; cheap non-negative mod
__device__ __forceinline__ int slot4(int p) { return (p + 4) & 3; }
__device__ __forceinline__ int slot3(int p) { return (p + 3) % 3; }

// ---- stage one u/T plane (global -> smem), direct ----
__device__ __forceinline__ void stage_direct(const float* __restrict__ u,
                                             const float* __restrict__ T,
                                             float* sU, int slot, int p,
                                             int sgb0, int suo0,
                                             int sgb1, int suo1, bool hasq1)
{
    const int zo = wrapg(p) * NN2;
    float* b = sU + slot * SU_PLANE;
    b[0 * PY2 * PX2 + suo0] = __ldg(u + 0 * NN3 + zo + sgb0);
    b[1 * PY2 * PX2 + suo0] = __ldg(u + 1 * NN3 + zo + sgb0);
    b[2 * PY2 * PX2 + suo0] = __ldg(u + 2 * NN3 + zo + sgb0);
    b[3 * PY2 * PX2 + suo0] = __ldg(T + zo + sgb0);
    if (hasq1) {
        b[0 * PY2 * PX2 + suo1] = __ldg(u + 0 * NN3 + zo + sgb1);
        b[1 * PY2 * PX2 + suo1] = __ldg(u + 1 * NN3 + zo + sgb1);
        b[2 * PY2 * PX2 + suo1] = __ldg(u + 2 * NN3 + zo + sgb1);
        b[3 * PY2 * PX2 + suo1] = __ldg(T + zo + sgb1);
    }
}

// ---- prefetch one u/T plane (global -> registers) ----
__device__ __forceinline__ void prefetch_plane(const float* __restrict__ u,
                                               const float* __restrict__ T,
                                               int p, int sgb0, int sgb1, bool hasq1,
                                               float pr0[4], float pr1[4])
{
    const int zo = wrapg(p) * NN2;
    pr0[0] = __ldg(u + 0 * NN3 + zo + sgb0);
    pr0[1] = __ldg(u + 1 * NN3 + zo + sgb0);
    pr0[2] = __ldg(u + 2 * NN3 + zo + sgb0);
    pr0[3] = __ldg(T + zo + sgb0);
    if (hasq1) {
        pr1[0] = __ldg(u + 0 * NN3 + zo + sgb1);
        pr1[1] = __ldg(u + 1 * NN3 + zo + sgb1);
        pr1[2] = __ldg(u + 2 * NN3 + zo + sgb1);
        pr1[3] = __ldg(T + zo + sgb1);
    }
}

__device__ __forceinline__ void sts_prefetch(float* sU, int slot,
                                             int suo0, int suo1, bool hasq1,
                                             const float pr0[4], const float pr1[4])
{
    float* b = sU + slot * SU_PLANE;
    b[0 * PY2 * PX2 + suo0] = pr0[0];
    b[1 * PY2 * PX2 + suo0] = pr0[1];
    b[2 * PY2 * PX2 + suo0] = pr0[2];
    b[3 * PY2 * PX2 + suo0] = pr0[3];
    if (hasq1) {
        b[0 * PY2 * PX2 + suo1] = pr1[0];
        b[1 * PY2 * PX2 + suo1] = pr1[1];
        b[2 * PY2 * PX2 + suo1] = pr1[2];
        b[3 * PY2 * PX2 + suo1] = pr1[3];
    }
}

// ---- flux math from gradients: writes 7 halo comps to smem, returns t00,t01,t02,E0 ----
__device__ __forceinline__ void flux_finish(const float c4[4], const float gz4[4],
                                            const float gy4[4], const float gx4[4],
                                            float* H, int ho, float fz[4])
{
    const float divu = gz4[0] + gy4[1] + gx4[2];
    const float mu   = MU_REF_F * __powf(c4[3], 0.7f);
    const float kk   = mu * CP_OVER_PR;
    const float lam  = -(2.0f / 3.0f) * mu * divu;

    const float t00 = 2.0f * mu * gz4[0] + lam;
    const float t11 = 2.0f * mu * gy4[1] + lam;
    const float t22 = 2.0f * mu * gx4[2] + lam;
    const float t01 = mu * (gy4[0] + gz4[1]);
    const float t02 = mu * (gx4[0] + gz4[2]);
    const float t12 = mu * (gx4[1] + gy4[2]);

    const float E0 = kk * gz4[3] + c4[0] * t00 + c4[1] * t01 + c4[2] * t02;
    const float E1 = kk * gy4[3] + c4[0] * t01 + c4[1] * t11 + c4[2] * t12;
    const float E2 = kk * gx4[3] + c4[0] * t02 + c4[1] * t12 + c4[2] * t22;

    H[0 * PY * PX + ho] = t01;
    H[1 * PY * PX + ho] = t02;
    H[2 * PY * PX + ho] = t11;
    H[3 * PY * PX + ho] = t12;
    H[4 * PY * PX + ho] = t22;
    H[5 * PY * PX + ho] = E1;
    H[6 * PY * PX + ho] = E2;

    fz[0] = t00; fz[1] = t01; fz[2] = t02; fz[3] = E0;
}

// ---- center-point flux: full-warp, x-derivs via shuffles ----
__device__ __forceinline__ void flux_center(const float* sU, float* sFh,
                                            int sm_, int sc_, int sp_, int fslot,
                                            int uoff, int ho, int tx, float fz[4])
{
    const float* Pm = sU + sm_ * SU_PLANE;
    const float* Pc = sU + sc_ * SU_PLANE;
    const float* Pp = sU + sp_ * SU_PLANE;

    float c4[4], gz4[4], gy4[4], gx4[4];
#pragma unroll
    for (int i = 0; i < 4; i++) {
        const float* Cm = Pm + i * PY2 * PX2;
        const float* Cc = Pc + i * PY2 * PX2;
        const float* Cp = Pp + i * PY2 * PX2;
        const float c = Cc[uoff];
        float xl = __shfl_up_sync(0xffffffffu, c, 1);
        if (tx == 0)  xl = Cc[uoff - 1];
        float xr = __shfl_down_sync(0xffffffffu, c, 1);
        if (tx == 31) xr = Cc[uoff + 1];
        c4[i]  = c;
        gz4[i] = (Cp[uoff] - Cm[uoff]) * INV2DX;
        gy4[i] = (Cc[uoff + PX2] - Cc[uoff - PX2]) * INV2DX;
        gx4[i] = (xr - xl) * INV2DX;
    }
    flux_finish(c4, gz4, gy4, gx4, sFh + fslot * SFH_PLANE, ho, fz);
}

// ---- halo-ring flux: generic LDS version ----
__device__ __forceinline__ void flux_halo(const float* sU, float* sFh,
                                          int sm_, int sc_, int sp_, int fslot,
                                          int uoff, int ho)
{
    const float* Pm = sU + sm_ * SU_PLANE;
    const float* Pc = sU + sc_ * SU_PLANE;
    const float* Pp = sU + sp_ * SU_PLANE;

    float c4[4], gz4[4], gy4[4], gx4[4];
#pragma unroll
    for (int i = 0; i < 4; i++) {
        const float* Cm = Pm + i * PY2 * PX2;
        const float* Cc = Pc + i * PY2 * PX2;
        const float* Cp = Pp + i * PY2 * PX2;
        c4[i]  = Cc[uoff];
        gz4[i] = (Cp[uoff] - Cm[uoff]) * INV2DX;
        gy4[i] = (Cc[uoff + PX2] - Cc[uoff - PX2]) * INV2DX;
        gx4[i] = (Cc[uoff + 1] - Cc[uoff - 1]) * INV2DX;
    }
    float fz_dummy[4];
    flux_finish(c4, gz4, gy4, gx4, sFh + fslot * SFH_PLANE, ho, fz_dummy);
}

__global__ void __launch_bounds__(NTHREADS, 4)
fused4(const float* __restrict__ u, const float* __restrict__ T, float* __restrict__ out)
{
    extern __shared__ float smem_pool[];
    float* sU  = smem_pool;                 // [4][4][PY2][PX2]
    float* sFh = smem_pool + 4 * SU_PLANE;  // [3][7][PY][PX]

    const int tid = threadIdx.y * TX + threadIdx.x;
    const int tx = threadIdx.x, ty = threadIdx.y;
    const int x0 = blockIdx.x * TX;
    const int y0 = blockIdx.y * TY;
    const int z0 = blockIdx.z * CHUNK;

    // ---- staging coords (2 points per thread) ----
    int sgb0, suo0, sgb1, suo1;
    bool hasq1;
    {
        const int q0 = tid;
        const int sy0 = q0 / PX2, sx0 = q0 - sy0 * PX2;
        sgb0 = wrapg(y0 + sy0 - 2) * NN + wrapg(x0 + sx0 - 2);
        suo0 = sy0 * PX2 + sx0;
        const int q1 = tid + NTHREADS;
        hasq1 = (q1 < PX2 * PY2);
        const int qq = hasq1 ? q1 : 0;
        const int sy1 = qq / PX2, sx1 = qq - sy1 * PX2;
        sgb1 = wrapg(y0 + sy1 - 2) * NN + wrapg(x0 + sx1 - 2);
        suo1 = sy1 * PX2 + sx1;
    }

    // ---- fill coords: job0 = own center, job1 = halo ring (tid < 84) ----
    const int cfy = ty + 1, cfx = tx + 1;
    const int uoffc = (cfy + 1) * PX2 + (cfx + 1);
    const int hoc   = cfy * PX + cfx;
    const bool hasH = (tid < NHALO);
    int uoffh = 0, hoh = 0;
    {
        int hfy, hfx;
        if (tid < PX)            { hfy = 0;      hfx = tid; }
        else if (tid < 2 * PX)   { hfy = PY - 1; hfx = tid - PX; }
        else                     { const int r = tid - 2 * PX;
                                   hfy = 1 + (r >> 1); hfx = (r & 1) ? (PX - 1) : 0; }
        uoffh = (hfy + 1) * PX2 + (hfx + 1);
        hoh   = hfy * PX + hfx;
    }

    float pr0[4], pr1[4];
    float fzm[4], fzc[4], fzp[4];

    // ================= prologue =================
    stage_direct(u, T, sU, slot4(z0 - 2), z0 - 2, sgb0, suo0, sgb1, suo1, hasq1);
    stage_direct(u, T, sU, slot4(z0 - 1), z0 - 1, sgb0, suo0, sgb1, suo1, hasq1);
    stage_direct(u, T, sU, slot4(z0),     z0,     sgb0, suo0, sgb1, suo1, hasq1);
    __syncthreads();

    // prefetch plane z0+1, fill flux z0-1 (reads slots z0-2..z0)
    prefetch_plane(u, T, z0 + 1, sgb0, sgb1, hasq1, pr0, pr1);
    flux_center(sU, sFh, slot4(z0 - 2), slot4(z0 - 1), slot4(z0), slot3(z0 - 1), uoffc, hoc, tx, fzm);
    if (hasH)
        flux_halo(sU, sFh, slot4(z0 - 2), slot4(z0 - 1), slot4(z0), slot3(z0 - 1), uoffh, hoh);
    // STS z0+1 into slot4(z0+1): disjoint from {z0-2, z0-1, z0} mod 4 -> no sync needed
    sts_prefetch(sU, slot4(z0 + 1), suo0, suo1, hasq1, pr0, pr1);
    __syncthreads();

    // prefetch plane z0+2, fill flux z0 (reads slots z0-1..z0+1)
    prefetch_plane(u, T, z0 + 2, sgb0, sgb1, hasq1, pr0, pr1);
    flux_center(sU, sFh, slot4(z0 - 1), slot4(z0), slot4(z0 + 1), slot3(z0), uoffc, hoc, tx, fzc);
    if (hasH)
        flux_halo(sU, sFh, slot4(z0 - 1), slot4(z0), slot4(z0 + 1), slot3(z0), uoffh, hoh);

    const int gx = x0 + tx, gy = y0 + ty;

    // ================= main loop: ONE sync per z-step =================
    for (int zi = 0; zi < CHUNK; zi++) {
        const int z = z0 + zi;

        // 1. commit prefetched plane z+2 into slot4(z+2).
        //    Laggard threads may still read slots {z-1, z, z+1} in the previous
        //    fill — all disjoint from slot4(z+2) mod 4. Safe without a sync.
        sts_prefetch(sU, slot4(z + 2), suo0, suo1, hasq1, pr0, pr1);
        __syncthreads();

        // 2. prefetch plane z+3 (latency overlapped with fill + output)
        if (zi + 1 < CHUNK)
            prefetch_plane(u, T, z + 3, sgb0, sgb1, hasq1, pr0, pr1);

        // 3. fill flux plane z+1 from sU slots z, z+1, z+2
        flux_center(sU, sFh, slot4(z), slot4(z + 1), slot4(z + 2), slot3(z + 1), uoffc, hoc, tx, fzp);
        if (hasH)
            flux_halo(sU, sFh, slot4(z), slot4(z + 1), slot4(z + 2), slot3(z + 1), uoffh, hoh);

        // 4. output plane z: y/x flux derivs from sFh slot3(z) (written at the
        //    previous iteration's fill; ordered by this iteration's sync),
        //    z-derivs from the register pipeline.
        const float* HB = sFh + slot3(z) * SFH_PLANE;

        const float mom0 = (fzp[0] - fzm[0])
                         + (HB[0 * PY * PX + hoc + PX] - HB[0 * PY * PX + hoc - PX])
                         + (HB[1 * PY * PX + hoc + 1]  - HB[1 * PY * PX + hoc - 1]);
        const float mom1 = (fzp[1] - fzm[1])
                         + (HB[2 * PY * PX + hoc + PX] - HB[2 * PY * PX + hoc - PX])
                         + (HB[3 * PY * PX + hoc + 1]  - HB[3 * PY * PX + hoc - 1]);
        const float mom2 = (fzp[2] - fzm[2])
                         + (HB[3 * PY * PX + hoc + PX] - HB[3 * PY * PX + hoc - PX])
                         + (HB[4 * PY * PX + hoc + 1]  - HB[4 * PY * PX + hoc - 1]);
        const float en   = (fzp[3] - fzm[3])
                         + (HB[5 * PY * PX + hoc + PX] - HB[5 * PY * PX + hoc - PX])
                         + (HB[6 * PY * PX + hoc + 1]  - HB[6 * PY * PX + hoc - 1]);

        const int idx = z * NN2 + gy * NN + gx;
        out[0 * NN3 + idx] = 0.0f;
        out[1 * NN3 + idx] = mom0 * INV2DX;
        out[2 * NN3 + idx] = mom1 * INV2DX;
        out[3 * NN3 + idx] = mom2 * INV2DX;
        out[4 * NN3 + idx] = en * INV2DX;

        // rotate register flux pipeline
#pragma unroll
        for (int c = 0; c < 4; c++) { fzm[c] = fzc[c]; fzc[c] = fzp[c]; }
    }
}

extern "C" void kernel_launch(void* const* d_in, const int* in_sizes, int n_in,
                              void* d_out, int out_size)
{
    const float* u = (const float*)d_in[0];   // [3, N, N, N]
    const float* T = (const float*)d_in[1];   // [N, N, N]
    float* out = (float*)d_out;               // [5, N, N, N]

    cudaFuncSetAttribute(fused4, cudaFuncAttributeMaxDynamicSharedMemorySize, SMEM_BYTES);

    dim3 grid(NN / TX, NN / TY, NN / CHUNK);  // 6 x 24 x 4 = 576 blocks
    dim3 block(TX, TY, 1);
    fused4<<<grid, block, SMEM_BYTES>>>(u, T, out);
}

// round 7
// speedup vs baseline: 1.2259x; 1.2259x over previous
#include <cuda_runtime.h>

#define NN  192
#define NN2 (NN*NN)
#define NN3 (NN*NN*NN)

#define INV2DX     96.0f          // 1/(2*dx), dx = 1/N
#define MU_REF_F   1.8e-5f
#define CP_OVER_PR 1395.833333f   // 1005 / 0.72

#define TX 32
#define TY 8
#define CHUNK 64
#define PX  (TX + 2)              // 34 flux-plane x extent (cols 0..33)
#define PY  (TY + 2)              // 10 flux-plane y extent (rows 0..9)
#define PX2 (TX + 4)              // 36 u/T staging x extent
#define PY2 (TY + 4)              // 12 u/T staging y extent
#define NSTG (PX2 * PY2)          // 432
#define NTHREADS (TX * TY)        // 256

__device__ __forceinline__ int wrapg(int i) { return (i < 0) ? i + NN : ((i >= NN) ? i - NN : i); }
__device__ __forceinline__ int slot4(int p) { return (p + 4) & 3; }

// fz = {t00,t01,t02,E0} (z-derivs), xq = {t02,t12,t22,E2} (x-derivs),
// yq = {t01,t11,t12,E1} (y-derivs)
__device__ __forceinline__ void flux_math(const float c4[4], const float gz4[4],
                                          const float gy4[4], const float gx4[4],
                                          float fz[4], float xq[4], float yq[4])
{
    const float divu = gz4[0] + gy4[1] + gx4[2];
    const float mu   = MU_REF_F * __powf(c4[3], 0.7f);
    const float kk   = mu * CP_OVER_PR;
    const float lam  = -(2.0f / 3.0f) * mu * divu;

    const float t00 = 2.0f * mu * gz4[0] + lam;
    const float t11 = 2.0f * mu * gy4[1] + lam;
    const float t22 = 2.0f * mu * gx4[2] + lam;
    const float t01 = mu * (gy4[0] + gz4[1]);
    const float t02 = mu * (gx4[0] + gz4[2]);
    const float t12 = mu * (gx4[1] + gy4[2]);

    const float E0 = kk * gz4[3] + c4[0] * t00 + c4[1] * t01 + c4[2] * t02;
    const float E1 = kk * gy4[3] + c4[0] * t01 + c4[1] * t11 + c4[2] * t12;
    const float E2 = kk * gx4[3] + c4[0] * t02 + c4[1] * t12 + c4[2] * t22;

    fz[0] = t00; fz[1] = t01; fz[2] = t02; fz[3] = E0;
    xq[0] = t02; xq[1] = t12; xq[2] = t22; xq[3] = E2;
    yq[0] = t01; yq[1] = t11; yq[2] = t12; yq[3] = E1;
}

__global__ void __launch_bounds__(NTHREADS)
fused5(const float* __restrict__ u, const float* __restrict__ T, float* __restrict__ out)
{
    __shared__ float sU[4][4][PY2][PX2];     // 4 rotating u/T plane slots  (27.6 KB)
    __shared__ float sFy[2][4][PY][TX];      // y-comps, 2 rotating slots   (10.2 KB)
    __shared__ float sFx[2][4][TY][2];       // x-comps at edge cols fx=0,33 (0.5 KB)

    const int tid = threadIdx.y * TX + threadIdx.x;
    const int tx = threadIdx.x, ty = threadIdx.y;
    const int x0 = blockIdx.x * TX;
    const int y0 = blockIdx.y * TY;
    const int z0 = blockIdx.z * CHUNK;

    // ---- staging coords (2 jobs per thread over PY2 x PX2) ----
    int sgb0, suo0, sgb1, suo1;
    bool hasq1;
    {
        const int sy0 = tid / PX2, sx0 = tid - sy0 * PX2;
        sgb0 = wrapg(y0 + sy0 - 2) * NN + wrapg(x0 + sx0 - 2);
        suo0 = sy0 * PX2 + sx0;
        const int q1 = tid + NTHREADS;
        hasq1 = (q1 < NSTG);
        const int qq = hasq1 ? q1 : 0;
        const int sy1 = qq / PX2, sx1 = qq - sy1 * PX2;
        sgb1 = wrapg(y0 + sy1 - 2) * NN + wrapg(x0 + sx1 - 2);
        suo1 = sy1 * PX2 + sx1;
    }

    // ---- center fill coords ----
    const int cfy = ty + 1;                       // flux row 1..8
    const int uoffc = (cfy + 1) * PX2 + (tx + 2); // u/T smem offset of own column

    // ---- halo job decode (tid < 80): 64 y-halo + 16 x-halo ----
    const bool isY = (tid < 64);
    const bool isH = (tid < 80);
    int uoffh = 0, hoff = 0, hstr = 0;
    {
        if (isY) {
            const int hfy = (tid >= 32) ? (PY - 1) : 0;   // flux rows 0 / 9
            const int hfx = 1 + (tid & 31);               // flux cols 1..32
            uoffh = (hfy + 1) * PX2 + (hfx + 1);
            hoff  = hfy * TX + (hfx - 1);
            hstr  = PY * TX;
        } else if (isH) {
            const int r = tid - 64;
            const int side = r >> 3;                      // 0: fx=0, 1: fx=33
            const int row  = r & 7;                       // flux row 1..8 -> idx row
            const int hfx  = side ? (PX - 1) : 0;
            uoffh = (row + 2) * PX2 + (hfx + 1);
            hoff  = row * 2 + side;
            hstr  = TY * 2;
        }
    }

    float pr0[4], pr1[4];
    float vm[4], vc[4], vp[4];                 // u/T register z-pipeline (own column)
    float fzm[4], fzc[4], fzp[4];              // {t00,t01,t02,E0} pipeline
    float xq_c[4], xq_n[4];                    // {t02,t12,t22,E2} at plane z / z+1

    // ============================ prologue ============================
    // stage planes z0-2, z0-1, z0
#pragma unroll
    for (int k = 0; k < 3; k++) {
        const int p = z0 - 2 + k;
        const int zo = wrapg(p) * NN2;
        float* b = &sU[slot4(p)][0][0][0];
        b[0 * PY2 * PX2 + suo0] = __ldg(u + 0 * NN3 + zo + sgb0);
        b[1 * PY2 * PX2 + suo0] = __ldg(u + 1 * NN3 + zo + sgb0);
        b[2 * PY2 * PX2 + suo0] = __ldg(u + 2 * NN3 + zo + sgb0);
        b[3 * PY2 * PX2 + suo0] = __ldg(T + zo + sgb0);
        if (hasq1) {
            b[0 * PY2 * PX2 + suo1] = __ldg(u + 0 * NN3 + zo + sgb1);
            b[1 * PY2 * PX2 + suo1] = __ldg(u + 1 * NN3 + zo + sgb1);
            b[2 * PY2 * PX2 + suo1] = __ldg(u + 2 * NN3 + zo + sgb1);
            b[3 * PY2 * PX2 + suo1] = __ldg(T + zo + sgb1);
        }
    }
    __syncthreads();

    // init register pipeline from planes z0-2 (vm) and z0-1 (vc)
#pragma unroll
    for (int i = 0; i < 4; i++) {
        vm[i] = sU[slot4(z0 - 2)][i][0][uoffc];
        vc[i] = sU[slot4(z0 - 1)][i][0][uoffc];
    }

    // prefetch plane z0+1
    {
        const int zo = wrapg(z0 + 1) * NN2;
        pr0[0] = __ldg(u + 0 * NN3 + zo + sgb0);
        pr0[1] = __ldg(u + 1 * NN3 + zo + sgb0);
        pr0[2] = __ldg(u + 2 * NN3 + zo + sgb0);
        pr0[3] = __ldg(T + zo + sgb0);
        if (hasq1) {
            pr1[0] = __ldg(u + 0 * NN3 + zo + sgb1);
            pr1[1] = __ldg(u + 1 * NN3 + zo + sgb1);
            pr1[2] = __ldg(u + 2 * NN3 + zo + sgb1);
            pr1[3] = __ldg(T + zo + sgb1);
        }
    }

    // fill plane z0-1: center only, keep fz only (y/x comps of z0-1 never read)
    {
        const float (*Uc)[PY2][PX2] = sU[slot4(z0 - 1)];
        const float (*Up)[PY2][PX2] = sU[slot4(z0)];
        float c4[4], gz4[4], gy4[4], gx4[4], xq_d[4], yq_d[4];
#pragma unroll
        for (int i = 0; i < 4; i++) {
            const float* Cc = &Uc[i][0][0];
            vp[i]  = (&Up[i][0][0])[uoffc];
            gz4[i] = (vp[i] - vm[i]) * INV2DX;
            gy4[i] = (Cc[uoffc + PX2] - Cc[uoffc - PX2]) * INV2DX;
            const float c = vc[i];
            float xl = __shfl_up_sync(0xffffffffu, c, 1);
            if (tx == 0)  xl = Cc[uoffc - 1];
            float xr = __shfl_down_sync(0xffffffffu, c, 1);
            if (tx == 31) xr = Cc[uoffc + 1];
            gx4[i] = (xr - xl) * INV2DX;
            c4[i] = c;
        }
        flux_math(c4, gz4, gy4, gx4, fzm, xq_d, yq_d);
#pragma unroll
        for (int i = 0; i < 4; i++) { vm[i] = vc[i]; vc[i] = vp[i]; }
    }

    // commit plane z0+1 (slot disjoint from all live reads)
    {
        float* b = &sU[slot4(z0 + 1)][0][0][0];
        b[0 * PY2 * PX2 + suo0] = pr0[0];
        b[1 * PY2 * PX2 + suo0] = pr0[1];
        b[2 * PY2 * PX2 + suo0] = pr0[2];
        b[3 * PY2 * PX2 + suo0] = pr0[3];
        if (hasq1) {
            b[0 * PY2 * PX2 + suo1] = pr1[0];
            b[1 * PY2 * PX2 + suo1] = pr1[1];
            b[2 * PY2 * PX2 + suo1] = pr1[2];
            b[3 * PY2 * PX2 + suo1] = pr1[3];
        }
    }
    __syncthreads();

    // prefetch plane z0+2
    {
        const int zo = wrapg(z0 + 2) * NN2;
        pr0[0] = __ldg(u + 0 * NN3 + zo + sgb0);
        pr0[1] = __ldg(u + 1 * NN3 + zo + sgb0);
        pr0[2] = __ldg(u + 2 * NN3 + zo + sgb0);
        pr0[3] = __ldg(T + zo + sgb0);
        if (hasq1) {
            pr1[0] = __ldg(u + 0 * NN3 + zo + sgb1);
            pr1[1] = __ldg(u + 1 * NN3 + zo + sgb1);
            pr1[2] = __ldg(u + 2 * NN3 + zo + sgb1);
            pr1[3] = __ldg(T + zo + sgb1);
        }
    }

    // fill plane z0: full (center stores y-comps; halo jobs store y/x comps)
    {
        const int s = z0 & 1;
        const float (*Uc)[PY2][PX2] = sU[slot4(z0)];
        const float (*Up)[PY2][PX2] = sU[slot4(z0 + 1)];
        float c4[4], gz4[4], gy4[4], gx4[4], yq[4];
#pragma unroll
        for (int i = 0; i < 4; i++) {
            const float* Cc = &Uc[i][0][0];
            vp[i]  = (&Up[i][0][0])[uoffc];
            gz4[i] = (vp[i] - vm[i]) * INV2DX;
            gy4[i] = (Cc[uoffc + PX2] - Cc[uoffc - PX2]) * INV2DX;
            const float c = vc[i];
            float xl = __shfl_up_sync(0xffffffffu, c, 1);
            if (tx == 0)  xl = Cc[uoffc - 1];
            float xr = __shfl_down_sync(0xffffffffu, c, 1);
            if (tx == 31) xr = Cc[uoffc + 1];
            gx4[i] = (xr - xl) * INV2DX;
            c4[i] = c;
        }
        flux_math(c4, gz4, gy4, gx4, fzc, xq_c, yq);
#pragma unroll
        for (int i = 0; i < 4; i++) sFy[s][i][cfy][tx] = yq[i];
#pragma unroll
        for (int i = 0; i < 4; i++) { vm[i] = vc[i]; vc[i] = vp[i]; }

        if (isH) {
            const float (*Um)[PY2][PX2] = sU[slot4(z0 - 1)];
            float h4[4], hz[4], hy[4], hx[4], hfz[4], hxq[4], hyq[4];
#pragma unroll
            for (int i = 0; i < 4; i++) {
                const float* Cm = &Um[i][0][0];
                const float* Cc = &Uc[i][0][0];
                const float* Cp = &Up[i][0][0];
                h4[i] = Cc[uoffh];
                hz[i] = (Cp[uoffh] - Cm[uoffh]) * INV2DX;
                hy[i] = (Cc[uoffh + PX2] - Cc[uoffh - PX2]) * INV2DX;
                hx[i] = (Cc[uoffh + 1] - Cc[uoffh - 1]) * INV2DX;
            }
            flux_math(h4, hz, hy, hx, hfz, hxq, hyq);
            float* hd = isY ? (&sFy[s][0][0][0] + hoff) : (&sFx[s][0][0][0] + hoff);
#pragma unroll
            for (int i = 0; i < 4; i++) hd[i * hstr] = isY ? hyq[i] : hxq[i];
        }
    }

    const int gx = x0 + tx, gy = y0 + ty;

    // ============================ main loop ============================
    for (int zi = 0; zi < CHUNK; zi++) {
        const int z = z0 + zi;

        // 1. commit prefetched plane z+2 (slot disjoint from live reads)
        {
            float* b = &sU[slot4(z + 2)][0][0][0];
            b[0 * PY2 * PX2 + suo0] = pr0[0];
            b[1 * PY2 * PX2 + suo0] = pr0[1];
            b[2 * PY2 * PX2 + suo0] = pr0[2];
            b[3 * PY2 * PX2 + suo0] = pr0[3];
            if (hasq1) {
                b[0 * PY2 * PX2 + suo1] = pr1[0];
                b[1 * PY2 * PX2 + suo1] = pr1[1];
                b[2 * PY2 * PX2 + suo1] = pr1[2];
                b[3 * PY2 * PX2 + suo1] = pr1[3];
            }
        }
        __syncthreads();

        // 2. prefetch plane z+3
        if (zi + 1 < CHUNK) {
            const int zo = wrapg(z + 3) * NN2;
            pr0[0] = __ldg(u + 0 * NN3 + zo + sgb0);
            pr0[1] = __ldg(u + 1 * NN3 + zo + sgb0);
            pr0[2] = __ldg(u + 2 * NN3 + zo + sgb0);
            pr0[3] = __ldg(T + zo + sgb0);
            if (hasq1) {
                pr1[0] = __ldg(u + 0 * NN3 + zo + sgb1);
                pr1[1] = __ldg(u + 1 * NN3 + zo + sgb1);
                pr1[2] = __ldg(u + 2 * NN3 + zo + sgb1);
                pr1[3] = __ldg(T + zo + sgb1);
            }
        }

        // 3. fill flux plane z+1
        {
            const int s1 = (z + 1) & 1;
            const float (*Uc)[PY2][PX2] = sU[slot4(z + 1)];
            const float (*Up)[PY2][PX2] = sU[slot4(z + 2)];
            float c4[4], gz4[4], gy4[4], gx4[4], yq[4];
#pragma unroll
            for (int i = 0; i < 4; i++) {
                const float* Cc = &Uc[i][0][0];
                vp[i]  = (&Up[i][0][0])[uoffc];
                gz4[i] = (vp[i] - vm[i]) * INV2DX;
                gy4[i] = (Cc[uoffc + PX2] - Cc[uoffc - PX2]) * INV2DX;
                const float c = vc[i];
                float xl = __shfl_up_sync(0xffffffffu, c, 1);
                if (tx == 0)  xl = Cc[uoffc - 1];
                float xr = __shfl_down_sync(0xffffffffu, c, 1);
                if (tx == 31) xr = Cc[uoffc + 1];
                gx4[i] = (xr - xl) * INV2DX;
                c4[i] = c;
            }
            flux_math(c4, gz4, gy4, gx4, fzp, xq_n, yq);
#pragma unroll
            for (int i = 0; i < 4; i++) sFy[s1][i][cfy][tx] = yq[i];

            if (isH) {
                const float (*Um)[PY2][PX2] = sU[slot4(z)];
                float h4[4], hz[4], hy[4], hx[4], hfz[4], hxq[4], hyq[4];
#pragma unroll
                for (int i = 0; i < 4; i++) {
                    const float* Cm = &Um[i][0][0];
                    const float* Cc = &Uc[i][0][0];
                    const float* Cp = &Up[i][0][0];
                    h4[i] = Cc[uoffh];
                    hz[i] = (Cp[uoffh] - Cm[uoffh]) * INV2DX;
                    hy[i] = (Cc[uoffh + PX2] - Cc[uoffh - PX2]) * INV2DX;
                    hx[i] = (Cc[uoffh + 1] - Cc[uoffh - 1]) * INV2DX;
                }
                flux_math(h4, hz, hy, hx, hfz, hxq, hyq);
                float* hd = isY ? (&sFy[s1][0][0][0] + hoff) : (&sFx[s1][0][0][0] + hoff);
#pragma unroll
                for (int i = 0; i < 4; i++) hd[i * hstr] = isY ? hyq[i] : hxq[i];
            }
        }

        // 4. output plane z
        {
            const int s = z & 1;
            float dy[4], xl[4], xr[4];
#pragma unroll
            for (int i = 0; i < 4; i++) {
                dy[i] = sFy[s][i][cfy + 1][tx] - sFy[s][i][cfy - 1][tx];
                xl[i] = __shfl_up_sync(0xffffffffu, xq_c[i], 1);
                if (tx == 0)  xl[i] = sFx[s][i][ty][0];
                xr[i] = __shfl_down_sync(0xffffffffu, xq_c[i], 1);
                if (tx == 31) xr[i] = sFx[s][i][ty][1];
            }

            const float mom0 = (fzp[0] - fzm[0]) + dy[0] + (xr[0] - xl[0]);
            const float mom1 = (fzp[1] - fzm[1]) + dy[1] + (xr[1] - xl[1]);
            const float mom2 = (fzp[2] - fzm[2]) + dy[2] + (xr[2] - xl[2]);
            const float en   = (fzp[3] - fzm[3]) + dy[3] + (xr[3] - xl[3]);

            const int idx = z * NN2 + gy * NN + gx;
            out[0 * NN3 + idx] = 0.0f;
            out[1 * NN3 + idx] = mom0 * INV2DX;
            out[2 * NN3 + idx] = mom1 * INV2DX;
            out[3 * NN3 + idx] = mom2 * INV2DX;
            out[4 * NN3 + idx] = en * INV2DX;
        }

        // 5. rotate pipelines
#pragma unroll
        for (int i = 0; i < 4; i++) {
            fzm[i] = fzc[i]; fzc[i] = fzp[i];
            xq_c[i] = xq_n[i];
            vm[i] = vc[i]; vc[i] = vp[i];
        }
    }
}

extern "C" void kernel_launch(void* const* d_in, const int* in_sizes, int n_in,
                              void* d_out, int out_size)
{
    const float* u = (const float*)d_in[0];   // [3, N, N, N]
    const float* T = (const float*)d_in[1];   // [N, N, N]
    float* out = (float*)d_out;               // [5, N, N, N]

    dim3 grid(NN / TX, NN / TY, NN / CHUNK);  // 6 x 24 x 3 = 432 blocks
    dim3 block(TX, TY, 1);
    fused5<<<grid, block>>>(u, T, out);
}

// round 8
// speedup vs baseline: 1.4453x; 1.1790x over previous
#include <cuda_runtime.h>

#define NN  192
#define NN2 (NN*NN)
#define NN3 (NN*NN*NN)

#define INV2DX     96.0f          // 1/(2*dx), dx = 1/N
#define MU_REF_F   1.8e-5f
#define CP_OVER_PR 1395.833333f   // 1005 / 0.72

#define TX 32
#define TY 8
#define CHUNK 64
#define PX  (TX + 2)              // 34 flux-plane x extent
#define PY  (TY + 2)              // 10 flux-plane y extent
#define PX2 (TX + 4)              // 36 u/T staging x extent
#define PY2 (TY + 4)              // 12 u/T staging y extent
#define NSTG (PX2 * PY2)          // 432
#define NTHREADS (TX * TY)        // 256

__device__ __forceinline__ int wrapg(int i) { return (i < 0) ? i + NN : ((i >= NN) ? i - NN : i); }
__device__ __forceinline__ int slot4(int p) { return (p + 4) & 3; }

__device__ __forceinline__ float4 f4diff(float4 a, float4 b) {
    return make_float4((a.x - b.x) * INV2DX, (a.y - b.y) * INV2DX,
                       (a.z - b.z) * INV2DX, (a.w - b.w) * INV2DX);
}

// c = {u0,u1,u2,T};  gz/gy/gx = gradients of the same 4 fields.
// fz = {t00,t01,t02,E0}, xq = {t02,t12,t22,E2}, yq = {t01,t11,t12,E1}
__device__ __forceinline__ void flux_math4(const float4 c, const float4 gz,
                                           const float4 gy, const float4 gx,
                                           float4& fz, float4& xq, float4& yq)
{
    const float divu = gz.x + gy.y + gx.z;
    const float mu   = MU_REF_F * __powf(c.w, 0.7f);
    const float kk   = mu * CP_OVER_PR;
    const float lam  = -(2.0f / 3.0f) * mu * divu;

    const float t00 = 2.0f * mu * gz.x + lam;
    const float t11 = 2.0f * mu * gy.y + lam;
    const float t22 = 2.0f * mu * gx.z + lam;
    const float t01 = mu * (gy.x + gz.y);
    const float t02 = mu * (gx.x + gz.z);
    const float t12 = mu * (gx.y + gy.z);

    const float E0 = kk * gz.w + c.x * t00 + c.y * t01 + c.z * t02;
    const float E1 = kk * gy.w + c.x * t01 + c.y * t11 + c.z * t12;
    const float E2 = kk * gx.w + c.x * t02 + c.y * t12 + c.z * t22;

    fz = make_float4(t00, t01, t02, E0);
    xq = make_float4(t02, t12, t22, E2);
    yq = make_float4(t01, t11, t12, E1);
}

__global__ void __launch_bounds__(NTHREADS)
fused6(const float* __restrict__ u, const float* __restrict__ T, float* __restrict__ out)
{
    __shared__ float4 sU[4][PY2 * PX2];   // 4 rotating u/T plane slots, AoS (27.6 KB)
    __shared__ float4 sFy[2][PY][TX];     // y-flux comps {t01,t11,t12,E1}   (10.2 KB)
    __shared__ float4 sFx[2][TY][2];      // x-flux comps at edge cols        (0.5 KB)

    const int tid = threadIdx.y * TX + threadIdx.x;
    const int tx = threadIdx.x, ty = threadIdx.y;
    const int x0 = blockIdx.x * TX;
    const int y0 = blockIdx.y * TY;
    const int z0 = blockIdx.z * CHUNK;

    // ---- staging coords (2 jobs per thread over PY2 x PX2) ----
    int sgb0, suo0, sgb1, suo1;
    bool hasq1;
    {
        const int sy0 = tid / PX2, sx0 = tid - sy0 * PX2;
        sgb0 = wrapg(y0 + sy0 - 2) * NN + wrapg(x0 + sx0 - 2);
        suo0 = sy0 * PX2 + sx0;
        const int q1 = tid + NTHREADS;
        hasq1 = (q1 < NSTG);
        const int qq = hasq1 ? q1 : 0;
        const int sy1 = qq / PX2, sx1 = qq - sy1 * PX2;
        sgb1 = wrapg(y0 + sy1 - 2) * NN + wrapg(x0 + sx1 - 2);
        suo1 = sy1 * PX2 + sx1;
    }

    // ---- center fill coords ----
    const int cfy = ty + 1;                            // flux row 1..8
    const int uoffc = (cfy + 1) * PX2 + (tx + 2);      // AoS point index

    // ---- halo job decode (tid < 80): 64 y-halo + 16 x-halo ----
    const bool isY = (tid < 64);
    const bool isH = (tid < 80);
    int uoffh = 0, hy_r = 0, hy_c = 0, hx_r = 0, hx_s = 0;
    {
        if (isY) {
            const int hfy = (tid >= 32) ? (PY - 1) : 0;   // flux rows 0 / 9
            const int hfx = 1 + (tid & 31);               // flux cols 1..32
            uoffh = (hfy + 1) * PX2 + (hfx + 1);
            hy_r = hfy; hy_c = hfx - 1;
        } else if (isH) {
            const int r = tid - 64;
            hx_s = r >> 3;                                // 0: fx=0, 1: fx=33
            hx_r = r & 7;                                 // rows 0..7
            const int hfx = hx_s ? (PX - 1) : 0;
            uoffh = (hx_r + 2) * PX2 + (hfx + 1);
        }
    }

    float4 pr0, pr1;                    // prefetch registers
    float4 vm, vc, vp;                  // u/T register z-pipeline (own column)
    float4 fzm, fzc, fzp;               // {t00,t01,t02,E0} pipeline
    float4 xq_c, xq_n;                  // {t02,t12,t22,E2} at plane z / z+1

    // ---- gmem plane load into registers ----
    auto ld_plane = [&](int p, float4& a, float4& b) {
        const int zo = wrapg(p) * NN2;
        a.x = u[0 * NN3 + zo + sgb0];
        a.y = u[1 * NN3 + zo + sgb0];
        a.z = u[2 * NN3 + zo + sgb0];
        a.w = T[zo + sgb0];
        if (hasq1) {
            b.x = u[0 * NN3 + zo + sgb1];
            b.y = u[1 * NN3 + zo + sgb1];
            b.z = u[2 * NN3 + zo + sgb1];
            b.w = T[zo + sgb1];
        }
    };
    auto commit = [&](int slot, const float4 a, const float4 b) {
        sU[slot][suo0] = a;
        if (hasq1) sU[slot][suo1] = b;
    };

    // ---- center-column flux fill (x-derivs via shfl of register column) ----
    auto fill_center = [&](int sc_, int sp_, float4& fz_o, float4& xq_o, int s1, bool storeY) {
        const float4* Uc = sU[sc_];
        const float4* Up = sU[sp_];
        const float4 vpv = Up[uoffc];
        const float4 gz  = f4diff(vpv, vm);
        const float4 gy  = f4diff(Uc[uoffc + PX2], Uc[uoffc - PX2]);
        float4 xl, xr;
        xl.x = __shfl_up_sync(0xffffffffu, vc.x, 1);
        xl.y = __shfl_up_sync(0xffffffffu, vc.y, 1);
        xl.z = __shfl_up_sync(0xffffffffu, vc.z, 1);
        xl.w = __shfl_up_sync(0xffffffffu, vc.w, 1);
        xr.x = __shfl_down_sync(0xffffffffu, vc.x, 1);
        xr.y = __shfl_down_sync(0xffffffffu, vc.y, 1);
        xr.z = __shfl_down_sync(0xffffffffu, vc.z, 1);
        xr.w = __shfl_down_sync(0xffffffffu, vc.w, 1);
        if (tx == 0)  xl = Uc[uoffc - 1];
        if (tx == 31) xr = Uc[uoffc + 1];
        const float4 gx = f4diff(xr, xl);
        float4 yq;
        flux_math4(vc, gz, gy, gx, fz_o, xq_o, yq);
        if (storeY) sFy[s1][cfy][tx] = yq;
        vp = vpv;
    };

    // ---- halo flux fill (pure AoS LDS) ----
    auto fill_halo = [&](int sm_, int sc_, int sp_, int s1) {
        const float4* Um = sU[sm_];
        const float4* Uc = sU[sc_];
        const float4* Up = sU[sp_];
        const float4 hc = Uc[uoffh];
        const float4 gz = f4diff(Up[uoffh], Um[uoffh]);
        const float4 gy = f4diff(Uc[uoffh + PX2], Uc[uoffh - PX2]);
        const float4 gx = f4diff(Uc[uoffh + 1], Uc[uoffh - 1]);
        float4 hfz, hxq, hyq;
        flux_math4(hc, gz, gy, gx, hfz, hxq, hyq);
        if (isY) sFy[s1][hy_r][hy_c] = hyq;
        else     sFx[s1][hx_r][hx_s] = hxq;
    };

    // ============================ prologue ============================
    {
        float4 a, b;
        ld_plane(z0 - 2, a, b); commit(slot4(z0 - 2), a, b);
        ld_plane(z0 - 1, a, b); commit(slot4(z0 - 1), a, b);
        ld_plane(z0,     a, b); commit(slot4(z0),     a, b);
    }
    __syncthreads();

    vm = sU[slot4(z0 - 2)][uoffc];
    vc = sU[slot4(z0 - 1)][uoffc];

    ld_plane(z0 + 1, pr0, pr1);
    // fill plane z0-1: center only, keep fz (y/x comps of z0-1 never read)
    {
        float4 xq_d;
        fill_center(slot4(z0 - 1), slot4(z0), fzm, xq_d, 0, false);
        vm = vc; vc = vp;
    }
    commit(slot4(z0 + 1), pr0, pr1);    // slot disjoint from all live reads
    __syncthreads();

    ld_plane(z0 + 2, pr0, pr1);
    // fill plane z0: full
    fill_center(slot4(z0), slot4(z0 + 1), fzc, xq_c, z0 & 1, true);
    if (isH) fill_halo(slot4(z0 - 1), slot4(z0), slot4(z0 + 1), z0 & 1);
    vm = vc; vc = vp;

    const int gx_ = x0 + tx, gy_ = y0 + ty;

    // ============================ main loop ============================
    for (int zi = 0; zi < CHUNK; zi++) {
        const int z = z0 + zi;

        // 1. commit prefetched plane z+2 (slot disjoint from laggard reads)
        commit(slot4(z + 2), pr0, pr1);
        __syncthreads();

        // 2. prefetch plane z+3
        if (zi + 1 < CHUNK) ld_plane(z + 3, pr0, pr1);

        // 3. fill flux plane z+1
        fill_center(slot4(z + 1), slot4(z + 2), fzp, xq_n, (z + 1) & 1, true);
        if (isH) fill_halo(slot4(z), slot4(z + 1), slot4(z + 2), (z + 1) & 1);

        // 4. output plane z
        {
            const int s = z & 1;
            const float4 yp = sFy[s][cfy + 1][tx];
            const float4 ym = sFy[s][cfy - 1][tx];
            float4 xl, xr;
            xl.x = __shfl_up_sync(0xffffffffu, xq_c.x, 1);
            xl.y = __shfl_up_sync(0xffffffffu, xq_c.y, 1);
            xl.z = __shfl_up_sync(0xffffffffu, xq_c.z, 1);
            xl.w = __shfl_up_sync(0xffffffffu, xq_c.w, 1);
            xr.x = __shfl_down_sync(0xffffffffu, xq_c.x, 1);
            xr.y = __shfl_down_sync(0xffffffffu, xq_c.y, 1);
            xr.z = __shfl_down_sync(0xffffffffu, xq_c.z, 1);
            xr.w = __shfl_down_sync(0xffffffffu, xq_c.w, 1);
            if (tx == 0)  xl = sFx[s][ty][0];
            if (tx == 31) xr = sFx[s][ty][1];

            const float mom0 = (fzp.x - fzm.x) + (yp.x - ym.x) + (xr.x - xl.x);
            const float mom1 = (fzp.y - fzm.y) + (yp.y - ym.y) + (xr.y - xl.y);
            const float mom2 = (fzp.z - fzm.z) + (yp.z - ym.z) + (xr.z - xl.z);
            const float en   = (fzp.w - fzm.w) + (yp.w - ym.w) + (xr.w - xl.w);

            const int idx = z * NN2 + gy_ * NN + gx_;
            out[0 * NN3 + idx] = 0.0f;
            out[1 * NN3 + idx] = mom0 * INV2DX;
            out[2 * NN3 + idx] = mom1 * INV2DX;
            out[3 * NN3 + idx] = mom2 * INV2DX;
            out[4 * NN3 + idx] = en * INV2DX;
        }

        // 5. rotate pipelines
        fzm = fzc; fzc = fzp;
        xq_c = xq_n;
        vm = vc; vc = vp;
    }
}

extern "C" void kernel_launch(void* const* d_in, const int* in_sizes, int n_in,
                              void* d_out, int out_size)
{
    const float* u = (const float*)d_in[0];   // [3, N, N, N]
    const float* T = (const float*)d_in[1];   // [N, N, N]
    float* out = (float*)d_out;               // [5, N, N, N]

    dim3 grid(NN / TX, NN / TY, NN / CHUNK);  // 6 x 24 x 3 = 432 blocks
    dim3 block(TX, TY, 1);
    fused6<<<grid, block>>>(u, T, out);
}